// round 10
// baseline (speedup 1.0000x reference)
#include <cuda_runtime.h>
#include <cuda_fp16.h>
#include <cuda_bf16.h>
#include <cstdint>

#define NN   100000
#define NE   600000
#define DD   128
#define NG   200
#define NLAY 5
#define NOUT 10
#define NBLK 98                 // ceil(NN/1024)
#define FILL_BLKS 1172          // ceil(NE/512)
#define EPI_BLKS  391           // ceil(NN/256)
#define GEMM_TILES 782          // ceil(NN/128)
#define PERS_BLKS 296           // 2 blocks/SM x 148 SMs (guaranteed co-resident)
#define BETAF 0.0077821404f     // ln(1 + 1/128)
#define OMBF  0.9922178596f     // 1 - BETA

// ---------------- scratch (device globals; no allocations) ----------------
// Zero-initialized at load; cleanup_kernel re-zeros at the END of every launch.
__device__ __align__(16) __half d_hsh[NN*DD];  // fp16: h * norm_out (gather table)
__device__ __align__(16) float  d_rst[NN*DD];
__device__ float d_norm_out[NN];
__device__ float d_sdeg[NN];
__device__ float d_norm_in [NN];
__device__ int   d_deg_out[NN];
__device__ int   d_deg_in [NN];
__device__ int   d_rowptr[NN+1];
__device__ int   d_cursor[NN];
__device__ int   d_col[NE];
__device__ float d_pooled[(NLAY+1)*NG*DD];
__device__ float d_bnsum[NLAY*2*DD];
__device__ int   d_pub[NBLK];                  // decoupled-lookback publish words
__device__ int   d_done[NLAY];                 // per-layer grid-barrier counters

// ---------------- degree histogram ----------------
__global__ void deg_kernel(const int* __restrict__ src, const int* __restrict__ dst) {
    int i = blockIdx.x * blockDim.x + threadIdx.x;
    if (i < NE) {
        atomicAdd(&d_deg_out[src[i]], 1);
        atomicAdd(&d_deg_in [dst[i]], 1);
    }
}

// ---------------- fused norms + single-pass exclusive scan (lookback) -------
__global__ __launch_bounds__(256) void scan_fused() {
    __shared__ int sh[256];
    __shared__ int spre[128];
    int t = threadIdx.x, b = blockIdx.x, base = b * 1024;

    int loc[4]; int s = 0;
    #pragma unroll
    for (int i = 0; i < 4; i++) {
        int idx = base + t * 4 + i;
        int v = 0;
        if (idx < NN) {
            int dgo = max(d_deg_out[idx], 1);
            d_norm_out[idx] = rsqrtf((float)dgo);
            d_sdeg[idx]     = sqrtf((float)dgo);
            v = d_deg_in[idx];
            d_norm_in[idx]  = rsqrtf((float)max(v, 1));
        }
        loc[i] = s; s += v;
    }
    sh[t] = s; __syncthreads();
    for (int off = 1; off < 256; off <<= 1) {
        int v = (t >= off) ? sh[t - off] : 0;
        __syncthreads();
        sh[t] += v;
        __syncthreads();
    }
    if (t == 0) atomicExch(&d_pub[b], sh[255] + 1);

    int myagg = 0;
    if (t < b) {
        volatile int* p = &d_pub[t];
        int v;
        do { v = *p; } while (v == 0);
        myagg = v - 1;
    }
    if (t < 128) spre[t] = myagg;
    __syncthreads();
    for (int off = 64; off > 0; off >>= 1) {
        if (t < off) spre[t] += spre[t + off];
        __syncthreads();
    }
    int bpre = spre[0];

    int tpre = (t == 0) ? 0 : sh[t - 1];
    #pragma unroll
    for (int i = 0; i < 4; i++) {
        int idx = base + t * 4 + i;
        if (idx < NN) { int p = bpre + tpre + loc[i]; d_rowptr[idx] = p; d_cursor[idx] = p; }
    }
    if (b == 0 && t == 0) d_rowptr[NN] = NE;
}

// ---------------- BN+ReLU epilogue body (TPB-templated) ----------------
template <bool INIT, int TPB>
__device__ __forceinline__ void epilogue_body(const float* __restrict__ src,
                                              const int* __restrict__ gid,
                                              int pslot,
                                              const float* __restrict__ bng,
                                              const float* __restrict__ bnb,
                                              const float* __restrict__ bnslot,
                                              int blk) {
    __shared__ float spool[16][128];
    const int QW = TPB / 128;          // node-interleave stride
    int t = threadIdx.x;
    int base = blk * 256;
    int nodes = min(256, NN - base);
    if (nodes <= 0) return;
    int g0 = gid[base];
    int span = gid[base + nodes - 1] - g0 + 1;
    bool fits = (span <= 16);
    if (fits) for (int i = t; i < span * 128; i += TPB) ((float*)spool)[i] = 0.f;
    __syncthreads();

    int d = t & 127;
    int q = t >> 7;   // 0..QW-1
    float bg = 0.f, bb = 0.f, mu = 0.f, is = 0.f;
    if (!INIT) {
        bg = bng[d]; bb = bnb[d];
        float s = bnslot[d], sq = bnslot[128 + d];
        mu = s * (1.0f / NN);
        is = rsqrtf(sq * (1.0f / NN) - mu * mu + 1e-5f);
    }
    const float* sp = INIT ? src : d_rst;

    float racc = 0.f; int rlg = -1;
    for (int i = q; i < nodes; i += QW) {
        int n = base + i;
        float v = sp[n * 128 + d];
        float y;
        if (INIT) y = v;
        else      y = fmaxf((v - mu) * is * bg + bb, 0.0f);
        d_hsh[n * 128 + d] = __float2half_rn(y * d_norm_out[n]);
        int lg = gid[n] - g0;
        if (fits) {
            if (lg != rlg) {
                if (rlg >= 0) atomicAdd(&spool[rlg][d], racc);
                rlg = lg; racc = 0.f;
            }
            racc += y;
        } else {
            atomicAdd(&d_pooled[(pslot * NG + g0 + lg) * 128 + d], y);
        }
    }
    if (fits && rlg >= 0) atomicAdd(&spool[rlg][d], racc);
    __syncthreads();
    if (fits)
        for (int lg = q; lg < span; lg += QW)
            atomicAdd(&d_pooled[(pslot * NG + g0 + lg) * 128 + d], spool[lg][d]);
    __syncthreads();
}

// fused: CSR fill (blocks [0,FILL_BLKS)) + init epilogue (blocks after)
__global__ __launch_bounds__(512) void fill_epi_kernel(const int* __restrict__ src,
                                                       const int* __restrict__ dst,
                                                       const float* __restrict__ feat,
                                                       const int* __restrict__ gid) {
    if (blockIdx.x < FILL_BLKS) {
        int i = blockIdx.x * 512 + threadIdx.x;
        if (i < NE) {
            int d = dst[i];
            int pos = atomicAdd(&d_cursor[d], 1);
            d_col[pos] = src[i];
        }
    } else {
        epilogue_body<true, 512>(feat, gid, 0, nullptr, nullptr, nullptr,
                                 blockIdx.x - FILL_BLKS);
    }
}

// ---------------- SpMM: half-warp per dst node, uint4 gathers ----------------
// 16 lanes x 16B = 256B per gather; 2 nodes/warp -> 2 overlapped chains,
// half the LDG/IMAD instruction stream vs the 32-lane uint2 version.
__global__ __launch_bounds__(256) void spmm_kernel() {
    int gw = (blockIdx.x * blockDim.x + threadIdx.x) >> 5;
    int lane = threadIdx.x & 31;
    int hw = lane >> 4, hl = lane & 15;
    int node = gw * 2 + hw;
    if (node >= NN) return;
    unsigned hmask = 0xFFFFu << (hw * 16);
    int beg = d_rowptr[node], end = d_rowptr[node + 1];
    float acc[8];
    #pragma unroll
    for (int k = 0; k < 8; k++) acc[k] = 0.f;
    const __half* hs = d_hsh;

    #define GATH(sv)                                                            \
        do {                                                                    \
            uint4 u = *reinterpret_cast<const uint4*>(hs + (sv) * 128 + hl * 8);\
            float2 f0 = __half22float2(*reinterpret_cast<__half2*>(&u.x));      \
            float2 f1 = __half22float2(*reinterpret_cast<__half2*>(&u.y));      \
            float2 f2 = __half22float2(*reinterpret_cast<__half2*>(&u.z));      \
            float2 f3 = __half22float2(*reinterpret_cast<__half2*>(&u.w));      \
            acc[0] += f0.x; acc[1] += f0.y; acc[2] += f1.x; acc[3] += f1.y;     \
            acc[4] += f2.x; acc[5] += f2.y; acc[6] += f3.x; acc[7] += f3.y;     \
        } while (0)

    for (int e0 = beg; e0 < end; e0 += 16) {
        int m = min(16, end - e0);
        int c = (hl < m) ? __ldg(&d_col[e0 + hl]) : 0;
        int j = 0;
        for (; j + 4 <= m; j += 4) {
            int s0 = __shfl_sync(hmask, c, j,     16);
            int s1 = __shfl_sync(hmask, c, j + 1, 16);
            int s2 = __shfl_sync(hmask, c, j + 2, 16);
            int s3 = __shfl_sync(hmask, c, j + 3, 16);
            GATH(s0); GATH(s1); GATH(s2); GATH(s3);
        }
        for (; j < m; j++) {
            int s = __shfl_sync(hmask, c, j, 16);
            GATH(s);
        }
    }
    float ni = 0.9f * d_norm_in[node];
    float rs = 0.1f * d_sdeg[node];
    // residual: h = hs[self] * sdeg
    {
        uint4 u = *reinterpret_cast<const uint4*>(hs + node * 128 + hl * 8);
        float2 f0 = __half22float2(*reinterpret_cast<__half2*>(&u.x));
        float2 f1 = __half22float2(*reinterpret_cast<__half2*>(&u.y));
        float2 f2 = __half22float2(*reinterpret_cast<__half2*>(&u.z));
        float2 f3 = __half22float2(*reinterpret_cast<__half2*>(&u.w));
        float4 y0, y1;
        y0.x = ni * acc[0] + rs * f0.x;  y0.y = ni * acc[1] + rs * f0.y;
        y0.z = ni * acc[2] + rs * f1.x;  y0.w = ni * acc[3] + rs * f1.y;
        y1.x = ni * acc[4] + rs * f2.x;  y1.y = ni * acc[5] + rs * f2.y;
        y1.z = ni * acc[6] + rs * f3.x;  y1.w = ni * acc[7] + rs * f3.y;
        float4* o = reinterpret_cast<float4*>(d_rst) + node * 32 + hl * 2;
        o[0] = y0; o[1] = y1;
    }
    #undef GATH
}

// ---------------- persistent fused GEMM + grid barrier + BN epilogue --------
// rst = (1-B)*rst + B*(rst@W) + bias; BN partials in registers across tiles;
// software grid barrier (exact-residency grid); then BN+ReLU+pool epilogue.
__global__ __launch_bounds__(256, 2) void gemm_epi_kernel(const float* __restrict__ W,
                                                          const float* __restrict__ bias,
                                                          float* __restrict__ bnslot,
                                                          const float* __restrict__ bng,
                                                          const float* __restrict__ bnb,
                                                          const int* __restrict__ gid,
                                                          int pslot, int* __restrict__ done) {
    __shared__ __align__(16) char usm[35840];   // union: (As+Ws) | Os | bns
    __nv_bfloat16 (*As)[72]  = reinterpret_cast<__nv_bfloat16(*)[72]>(usm);          // 18432B
    __nv_bfloat16 (*Ws)[136] = reinterpret_cast<__nv_bfloat16(*)[136]>(usm + 18432); // 17408B
    float (*Os)[132]         = reinterpret_cast<float(*)[132]>(usm);                 // 33792B
    float (*bns)[256]        = reinterpret_cast<float(*)[256]>(usm);                 // 8192B
    int t = threadIdx.x, lane = t & 31, wid = t >> 5;
    int c4 = t & 31;
    float4 bias4 = reinterpret_cast<const float4*>(bias)[c4];
    float sA[4] = {0.f, 0.f, 0.f, 0.f};
    float qA[4] = {0.f, 0.f, 0.f, 0.f};

    // ================= GEMM phase =================
    for (int tile = blockIdx.x; tile < GEMM_TILES; tile += PERS_BLKS) {
        int rowbase = tile * 128;
        float acc[16][4];
        #pragma unroll
        for (int i = 0; i < 16; i++) { acc[i][0]=0.f; acc[i][1]=0.f; acc[i][2]=0.f; acc[i][3]=0.f; }

        for (int kk = 0; kk < 128; kk += 64) {
            for (int i = t; i < 128 * 16; i += 256) {
                int r = i >> 4, cc = i & 15;
                int grow = rowbase + r;
                float4 v = make_float4(0.f, 0.f, 0.f, 0.f);
                if (grow < NN)
                    v = reinterpret_cast<const float4*>(d_rst)[grow * 32 + (kk >> 2) + cc];
                __nv_bfloat162* ap = reinterpret_cast<__nv_bfloat162*>(&As[r][cc * 4]);
                ap[0] = __floats2bfloat162_rn(v.x, v.y);
                ap[1] = __floats2bfloat162_rn(v.z, v.w);
            }
            for (int i = t; i < 64 * 32; i += 256) {
                int r = i >> 5, cc = i & 31;
                float4 v = reinterpret_cast<const float4*>(W)[(kk + r) * 32 + cc];
                __nv_bfloat162* wp = reinterpret_cast<__nv_bfloat162*>(&Ws[r][cc * 4]);
                wp[0] = __floats2bfloat162_rn(v.x, v.y);
                wp[1] = __floats2bfloat162_rn(v.z, v.w);
            }
            __syncthreads();

            #pragma unroll
            for (int k0 = 0; k0 < 64; k0 += 16) {
                uint32_t a[4];
                unsigned aaddr = (unsigned)__cvta_generic_to_shared(
                    &As[wid * 16 + (lane & 15)][k0 + ((lane >> 1) & 8)]);
                asm volatile("ldmatrix.sync.aligned.m8n8.x4.shared.b16 {%0,%1,%2,%3}, [%4];"
                             : "=r"(a[0]), "=r"(a[1]), "=r"(a[2]), "=r"(a[3]) : "r"(aaddr));
                unsigned bbase = (unsigned)__cvta_generic_to_shared(&Ws[k0 + (lane & 15)][0]);
                #pragma unroll
                for (int nb = 0; nb < 16; nb++) {
                    uint32_t b[2];
                    asm volatile("ldmatrix.sync.aligned.m8n8.x2.trans.shared.b16 {%0,%1}, [%2];"
                                 : "=r"(b[0]), "=r"(b[1]) : "r"(bbase + nb * 16));
                    asm volatile("mma.sync.aligned.m16n8k16.row.col.f32.bf16.bf16.f32 "
                                 "{%0,%1,%2,%3},{%4,%5,%6,%7},{%8,%9},{%0,%1,%2,%3};"
                                 : "+f"(acc[nb][0]), "+f"(acc[nb][1]), "+f"(acc[nb][2]), "+f"(acc[nb][3])
                                 : "r"(a[0]), "r"(a[1]), "r"(a[2]), "r"(a[3]), "r"(b[0]), "r"(b[1]));
                }
            }
            __syncthreads();
        }

        // staged epilogue: two 64-row passes through Os; coalesced rst RMW
        #pragma unroll
        for (int p = 0; p < 2; p++) {
            if ((wid >> 2) == p) {
                int r0 = (wid & 3) * 16 + (lane >> 2);
                #pragma unroll
                for (int nb = 0; nb < 16; nb++) {
                    int c = nb * 8 + (lane & 3) * 2;
                    *reinterpret_cast<float2*>(&Os[r0][c])     = make_float2(acc[nb][0], acc[nb][1]);
                    *reinterpret_cast<float2*>(&Os[r0 + 8][c]) = make_float2(acc[nb][2], acc[nb][3]);
                }
            }
            __syncthreads();
            #pragma unroll
            for (int it = 0; it < 8; it++) {
                int r = it * 8 + wid;
                int grow = rowbase + p * 64 + r;
                if (grow < NN) {
                    float4 rv = reinterpret_cast<const float4*>(d_rst)[grow * 32 + c4];
                    float4 av = *reinterpret_cast<const float4*>(&Os[r][c4 * 4]);
                    float4 y;
                    y.x = OMBF * rv.x + BETAF * av.x + bias4.x;
                    y.y = OMBF * rv.y + BETAF * av.y + bias4.y;
                    y.z = OMBF * rv.z + BETAF * av.z + bias4.z;
                    y.w = OMBF * rv.w + BETAF * av.w + bias4.w;
                    reinterpret_cast<float4*>(d_rst)[grow * 32 + c4] = y;
                    sA[0] += y.x; qA[0] += y.x * y.x;
                    sA[1] += y.y; qA[1] += y.y * y.y;
                    sA[2] += y.z; qA[2] += y.z * y.z;
                    sA[3] += y.w; qA[3] += y.w * y.w;
                }
            }
            __syncthreads();
        }
    }

    // block-level BN reduction (usm reused; all Os reads are behind syncthreads)
    #pragma unroll
    for (int j = 0; j < 4; j++) {
        bns[wid][c4 * 4 + j]       = sA[j];
        bns[wid][128 + c4 * 4 + j] = qA[j];
    }
    __syncthreads();
    {
        float v = 0.f;
        #pragma unroll
        for (int w = 0; w < 8; w++) v += bns[w][t];
        atomicAdd(&bnslot[t], v);
    }

    // ================= grid barrier =================
    __threadfence();
    __syncthreads();
    if (t == 0) {
        atomicAdd(done, 1);
        while (*(volatile int*)done < PERS_BLKS) __nanosleep(64);
    }
    __syncthreads();
    __threadfence();

    // ================= epilogue phase =================
    for (int blk = blockIdx.x; blk < EPI_BLKS; blk += PERS_BLKS)
        epilogue_body<false, 256>(nullptr, gid, pslot, bng, bnb, bnslot, blk);
}

// ---------------- readout ----------------
__global__ void final_kernel(const float* __restrict__ lin_w,
                             const float* __restrict__ lin_b,
                             float* __restrict__ out) {
    __shared__ float sp[6][128];
    __shared__ float sc[NOUT];
    int g = blockIdx.x, t = threadIdx.x;   // 128 threads
    for (int i = t; i < 6 * 128; i += 128)
        sp[i / 128][i & 127] = d_pooled[((i / 128) * NG + g) * 128 + (i & 127)];
    __syncthreads();
    if (t < NOUT) {
        float s = 0.f;
        for (int i = 0; i < 6; i++) {
            s += lin_b[i * NOUT + t];
            const float* w = lin_w + i * 128 * NOUT;
            float ps = 0.f;
            for (int k = 0; k < 128; k++) ps += sp[i][k] * w[k * NOUT + t];
            s += ps;
        }
        sc[t] = s;
    }
    __syncthreads();
    if (t < NOUT) {
        float m = sc[0];
        #pragma unroll
        for (int i = 1; i < NOUT; i++) m = fmaxf(m, sc[i]);
        float lse = 0.f;
        #pragma unroll
        for (int i = 0; i < NOUT; i++) lse += expf(sc[i] - m);
        lse = logf(lse);
        out[g * NOUT + t] = sc[t] - m - lse;
    }
    float mp = sp[1][t] + sp[2][t] + sp[3][t] + sp[4][t] + sp[5][t];
    out[NG * NOUT + g * 128 + t] = mp * 0.2f;
}

// ---------------- trailing cleanup: restore zero state for next replay -----
__global__ void cleanup_kernel() {
    int i = blockIdx.x * blockDim.x + threadIdx.x;
    if (i < NN) { d_deg_out[i] = 0; d_deg_in[i] = 0; }
    if (i < (NLAY+1)*NG*DD) d_pooled[i] = 0.f;
    if (i < NLAY*2*DD) d_bnsum[i] = 0.f;
    if (i < NBLK) d_pub[i] = 0;
    if (i < NLAY) d_done[i] = 0;
}

// ---------------- host launcher ----------------
extern "C" void kernel_launch(void* const* d_in, const int* in_sizes, int n_in,
                              void* d_out, int out_size) {
    const float* feat  = (const float*)d_in[0];
    const int*   src   = (const int*)  d_in[1];
    const int*   dst   = (const int*)  d_in[2];
    const int*   gid   = (const int*)  d_in[3];
    const float* gcn_w = (const float*)d_in[4];
    const float* gcn_b = (const float*)d_in[5];
    const float* bn_g  = (const float*)d_in[6];
    const float* bn_b  = (const float*)d_in[7];
    const float* lin_w = (const float*)d_in[8];
    const float* lin_b = (const float*)d_in[9];
    float* out = (float*)d_out;
    (void)in_sizes; (void)n_in; (void)out_size;

    float* bnsum_base;
    cudaGetSymbolAddress((void**)&bnsum_base, d_bnsum);
    int* done_base;
    cudaGetSymbolAddress((void**)&done_base, d_done);

    deg_kernel<<<(NE + 255) / 256, 256>>>(src, dst);
    scan_fused<<<NBLK, 256>>>();
    fill_epi_kernel<<<FILL_BLKS + EPI_BLKS, 512>>>(src, dst, feat, gid);

    for (int l = 0; l < NLAY; l++) {
        spmm_kernel<<<(NN / 2 * 32 + 255) / 256, 256>>>();
        gemm_epi_kernel<<<PERS_BLKS, 256>>>(gcn_w + l * DD * DD, gcn_b + l * DD,
                                            bnsum_base + l * 2 * DD,
                                            bn_g + l * DD, bn_b + l * DD,
                                            gid, l + 1, done_base + l);
    }
    final_kernel<<<NG, 128>>>(lin_w, lin_b, out);
    cleanup_kernel<<<600, 256>>>();
}

// round 11
// speedup vs baseline: 1.6090x; 1.6090x over previous
#include <cuda_runtime.h>
#include <cuda_fp16.h>
#include <cuda_bf16.h>
#include <cstdint>

#define NN   100000
#define NE   600000
#define DD   128
#define NG   200
#define NLAY 5
#define NOUT 10
#define NBLK 98                 // ceil(NN/1024)
#define FILL_BLKS 1172          // ceil(NE/512)
#define EPI_BLKS  391           // ceil(NN/256)
#define BETAF 0.0077821404f     // ln(1 + 1/128)
#define OMBF  0.9922178596f     // 1 - BETA

// ---------------- scratch (device globals; no allocations) ----------------
// Zero-initialized at load; cleanup_kernel re-zeros at the END of every launch.
__device__ __align__(16) __half d_hsh[NN*DD];  // fp16: h * norm_out (gather table)
__device__ __align__(16) float  d_rst[NN*DD];
__device__ __align__(16) __nv_bfloat16 d_wb[NLAY*DD*DD];  // bf16 weights
__device__ float d_norm_out[NN];
__device__ float d_sdeg[NN];
__device__ float d_norm_in [NN];
__device__ int   d_deg_out[NN];
__device__ int   d_deg_in [NN];
__device__ int   d_rowptr[NN+1];
__device__ int   d_cursor[NN];
__device__ int   d_col[NE];
__device__ float d_pooled[(NLAY+1)*NG*DD];
__device__ float d_bnsum[NLAY*2*DD];
__device__ int   d_pub[NBLK];                  // decoupled-lookback publish words

// ---------------- degree histogram ----------------
__global__ void deg_kernel(const int* __restrict__ src, const int* __restrict__ dst) {
    int i = blockIdx.x * blockDim.x + threadIdx.x;
    if (i < NE) {
        atomicAdd(&d_deg_out[src[i]], 1);
        atomicAdd(&d_deg_in [dst[i]], 1);
    }
}

// ---------------- fused norms + single-pass exclusive scan (lookback) -------
__global__ __launch_bounds__(256) void scan_fused() {
    __shared__ int sh[256];
    __shared__ int spre[128];
    int t = threadIdx.x, b = blockIdx.x, base = b * 1024;

    int loc[4]; int s = 0;
    #pragma unroll
    for (int i = 0; i < 4; i++) {
        int idx = base + t * 4 + i;
        int v = 0;
        if (idx < NN) {
            int dgo = max(d_deg_out[idx], 1);
            d_norm_out[idx] = rsqrtf((float)dgo);
            d_sdeg[idx]     = sqrtf((float)dgo);
            v = d_deg_in[idx];
            d_norm_in[idx]  = rsqrtf((float)max(v, 1));
        }
        loc[i] = s; s += v;
    }
    sh[t] = s; __syncthreads();
    for (int off = 1; off < 256; off <<= 1) {
        int v = (t >= off) ? sh[t - off] : 0;
        __syncthreads();
        sh[t] += v;
        __syncthreads();
    }
    if (t == 0) atomicExch(&d_pub[b], sh[255] + 1);

    int myagg = 0;
    if (t < b) {
        volatile int* p = &d_pub[t];
        int v;
        do { v = *p; } while (v == 0);
        myagg = v - 1;
    }
    if (t < 128) spre[t] = myagg;
    __syncthreads();
    for (int off = 64; off > 0; off >>= 1) {
        if (t < off) spre[t] += spre[t + off];
        __syncthreads();
    }
    int bpre = spre[0];

    int tpre = (t == 0) ? 0 : sh[t - 1];
    #pragma unroll
    for (int i = 0; i < 4; i++) {
        int idx = base + t * 4 + i;
        if (idx < NN) { int p = bpre + tpre + loc[i]; d_rowptr[idx] = p; d_cursor[idx] = p; }
    }
    if (b == 0 && t == 0) d_rowptr[NN] = NE;
}

// ---------------- W fp32 -> bf16 (all layers) ----------------
__global__ void wconv_kernel(const float* __restrict__ gcn_w) {
    int i = blockIdx.x * blockDim.x + threadIdx.x;
    if (i < NLAY * DD * DD) d_wb[i] = __float2bfloat16(gcn_w[i]);
}

// ---------------- BN+ReLU epilogue body ----------------
template <bool INIT, int TPB>
__device__ __forceinline__ void epilogue_body(const float* __restrict__ src,
                                              const int* __restrict__ gid,
                                              int pslot,
                                              const float* __restrict__ bng,
                                              const float* __restrict__ bnb,
                                              const float* __restrict__ bnslot,
                                              int blk, bool write_hs) {
    __shared__ float spool[16][128];
    const int QW = TPB / 128;
    int t = threadIdx.x;
    int base = blk * 256;
    int nodes = min(256, NN - base);
    if (nodes <= 0) return;
    int g0 = gid[base];
    int span = gid[base + nodes - 1] - g0 + 1;
    bool fits = (span <= 16);
    if (fits) for (int i = t; i < span * 128; i += TPB) ((float*)spool)[i] = 0.f;
    __syncthreads();

    int d = t & 127;
    int q = t >> 7;
    float bg = 0.f, bb = 0.f, mu = 0.f, is = 0.f;
    if (!INIT) {
        bg = bng[d]; bb = bnb[d];
        float s = bnslot[d], sq = bnslot[128 + d];
        mu = s * (1.0f / NN);
        is = rsqrtf(sq * (1.0f / NN) - mu * mu + 1e-5f);
    }
    const float* sp = INIT ? src : d_rst;

    float racc = 0.f; int rlg = -1;
    for (int i = q; i < nodes; i += QW) {
        int n = base + i;
        float v = sp[n * 128 + d];
        float y;
        if (INIT) y = v;
        else      y = fmaxf((v - mu) * is * bg + bb, 0.0f);
        if (write_hs) d_hsh[n * 128 + d] = __float2half_rn(y * d_norm_out[n]);
        int lg = gid[n] - g0;
        if (fits) {
            if (lg != rlg) {
                if (rlg >= 0) atomicAdd(&spool[rlg][d], racc);
                rlg = lg; racc = 0.f;
            }
            racc += y;
        } else {
            atomicAdd(&d_pooled[(pslot * NG + g0 + lg) * 128 + d], y);
        }
    }
    if (fits && rlg >= 0) atomicAdd(&spool[rlg][d], racc);
    __syncthreads();
    if (fits)
        for (int lg = q; lg < span; lg += QW)
            atomicAdd(&d_pooled[(pslot * NG + g0 + lg) * 128 + d], spool[lg][d]);
}

// fused: CSR fill (blocks [0,FILL_BLKS)) + init epilogue (blocks after)
__global__ __launch_bounds__(512) void fill_epi_kernel(const int* __restrict__ src,
                                                       const int* __restrict__ dst,
                                                       const float* __restrict__ feat,
                                                       const int* __restrict__ gid) {
    if (blockIdx.x < FILL_BLKS) {
        int i = blockIdx.x * 512 + threadIdx.x;
        if (i < NE) {
            int d = dst[i];
            int pos = atomicAdd(&d_cursor[d], 1);
            d_col[pos] = src[i];
        }
    } else {
        epilogue_body<true, 512>(feat, gid, 0, nullptr, nullptr, nullptr,
                                 blockIdx.x - FILL_BLKS, true);
    }
}

__global__ __launch_bounds__(512) void epilogue_kernel(const int* __restrict__ gid,
                                                       int pslot,
                                                       const float* __restrict__ bng,
                                                       const float* __restrict__ bnb,
                                                       const float* __restrict__ bnslot,
                                                       int write_hs) {
    epilogue_body<false, 512>(nullptr, gid, pslot, bng, bnb, bnslot,
                              blockIdx.x, write_hs != 0);
}

// ---------------- SpMM: warp per dst node, fp16 HADD2 accumulation ---------
// Per-chunk (<=32 edges) half2 partials flushed to fp32 -> bounded error,
// ~half the hot-loop instructions vs cvt+FADD.
__global__ __launch_bounds__(256) void spmm_kernel() {
    int warp = (blockIdx.x * blockDim.x + threadIdx.x) >> 5;
    int lane = threadIdx.x & 31;
    if (warp >= NN) return;
    int beg = d_rowptr[warp], end = d_rowptr[warp + 1];
    float4 acc = make_float4(0.f, 0.f, 0.f, 0.f);
    const __half* hs = d_hsh;

    for (int e0 = beg; e0 < end; e0 += 32) {
        int m = min(32, end - e0);
        int c = (lane < m) ? __ldg(&d_col[e0 + lane]) : 0;
        __half2 a0 = __float2half2_rn(0.f), a1 = a0;
        int j = 0;
        for (; j + 4 <= m; j += 4) {
            int s0 = __shfl_sync(0xffffffffu, c, j);
            int s1 = __shfl_sync(0xffffffffu, c, j + 1);
            int s2 = __shfl_sync(0xffffffffu, c, j + 2);
            int s3 = __shfl_sync(0xffffffffu, c, j + 3);
            uint2 u0 = *reinterpret_cast<const uint2*>(hs + s0 * 128 + lane * 4);
            uint2 u1 = *reinterpret_cast<const uint2*>(hs + s1 * 128 + lane * 4);
            uint2 u2 = *reinterpret_cast<const uint2*>(hs + s2 * 128 + lane * 4);
            uint2 u3 = *reinterpret_cast<const uint2*>(hs + s3 * 128 + lane * 4);
            a0 = __hadd2(a0, *reinterpret_cast<__half2*>(&u0.x));
            a1 = __hadd2(a1, *reinterpret_cast<__half2*>(&u0.y));
            a0 = __hadd2(a0, *reinterpret_cast<__half2*>(&u1.x));
            a1 = __hadd2(a1, *reinterpret_cast<__half2*>(&u1.y));
            a0 = __hadd2(a0, *reinterpret_cast<__half2*>(&u2.x));
            a1 = __hadd2(a1, *reinterpret_cast<__half2*>(&u2.y));
            a0 = __hadd2(a0, *reinterpret_cast<__half2*>(&u3.x));
            a1 = __hadd2(a1, *reinterpret_cast<__half2*>(&u3.y));
        }
        for (; j < m; j++) {
            int s = __shfl_sync(0xffffffffu, c, j);
            uint2 u = *reinterpret_cast<const uint2*>(hs + s * 128 + lane * 4);
            a0 = __hadd2(a0, *reinterpret_cast<__half2*>(&u.x));
            a1 = __hadd2(a1, *reinterpret_cast<__half2*>(&u.y));
        }
        float2 f0 = __half22float2(a0);
        float2 f1 = __half22float2(a1);
        acc.x += f0.x; acc.y += f0.y; acc.z += f1.x; acc.w += f1.y;
    }
    float ni = 0.9f * d_norm_in[warp];
    float rs = 0.1f * d_sdeg[warp];
    uint2 u = *reinterpret_cast<const uint2*>(hs + warp * 128 + lane * 4);
    float2 h0 = __half22float2(*reinterpret_cast<__half2*>(&u.x));
    float2 h1 = __half22float2(*reinterpret_cast<__half2*>(&u.y));
    float4 r;
    r.x = ni * acc.x + rs * h0.x;
    r.y = ni * acc.y + rs * h0.y;
    r.z = ni * acc.z + rs * h1.x;
    r.w = ni * acc.w + rs * h1.y;
    reinterpret_cast<float4*>(d_rst)[warp * 32 + lane] = r;
}

// ---------------- GEMM: rst = (1-B)*rst + B*(rst@W) + bias, in place -------
// W staged from precomputed bf16 (halved bytes, no per-block conversion).
// Staged smem epilogue (coalesced rst RMW) + register BN partials.
__global__ __launch_bounds__(256) void gemm_kernel(const __nv_bfloat16* __restrict__ Wb,
                                                   const float* __restrict__ bias,
                                                   float* __restrict__ bnslot) {
    __shared__ __align__(16) char usm[35840];   // union: (As+Ws) | Os
    __nv_bfloat16 (*As)[72]  = reinterpret_cast<__nv_bfloat16(*)[72]>(usm);          // 18432B
    __nv_bfloat16 (*Ws)[136] = reinterpret_cast<__nv_bfloat16(*)[136]>(usm + 18432); // 17408B
    float (*Os)[132]         = reinterpret_cast<float(*)[132]>(usm);                 // 33792B
    __shared__ float bns[8][256];
    int t = threadIdx.x, lane = t & 31, wid = t >> 5;
    int rowbase = blockIdx.x * 128;
    float acc[16][4];
    #pragma unroll
    for (int i = 0; i < 16; i++) { acc[i][0]=0.f; acc[i][1]=0.f; acc[i][2]=0.f; acc[i][3]=0.f; }

    for (int kk = 0; kk < 128; kk += 64) {
        for (int i = t; i < 128 * 16; i += 256) {
            int r = i >> 4, c4 = i & 15;
            int grow = rowbase + r;
            float4 v = make_float4(0.f, 0.f, 0.f, 0.f);
            if (grow < NN)
                v = reinterpret_cast<const float4*>(d_rst)[grow * 32 + (kk >> 2) + c4];
            __nv_bfloat162* ap = reinterpret_cast<__nv_bfloat162*>(&As[r][c4 * 4]);
            ap[0] = __floats2bfloat162_rn(v.x, v.y);
            ap[1] = __floats2bfloat162_rn(v.z, v.w);
        }
        for (int i = t; i < 64 * 16; i += 256) {   // 64 rows x 16 uint4 (8 bf16 each)
            int r = i >> 4, c8 = i & 15;
            uint4 v = reinterpret_cast<const uint4*>(Wb + (kk + r) * 128)[c8];
            *reinterpret_cast<uint4*>(&Ws[r][c8 * 8]) = v;
        }
        __syncthreads();

        #pragma unroll
        for (int k0 = 0; k0 < 64; k0 += 16) {
            uint32_t a[4];
            unsigned aaddr = (unsigned)__cvta_generic_to_shared(
                &As[wid * 16 + (lane & 15)][k0 + ((lane >> 1) & 8)]);
            asm volatile("ldmatrix.sync.aligned.m8n8.x4.shared.b16 {%0,%1,%2,%3}, [%4];"
                         : "=r"(a[0]), "=r"(a[1]), "=r"(a[2]), "=r"(a[3]) : "r"(aaddr));
            unsigned bbase = (unsigned)__cvta_generic_to_shared(&Ws[k0 + (lane & 15)][0]);
            #pragma unroll
            for (int nb = 0; nb < 16; nb++) {
                uint32_t b[2];
                asm volatile("ldmatrix.sync.aligned.m8n8.x2.trans.shared.b16 {%0,%1}, [%2];"
                             : "=r"(b[0]), "=r"(b[1]) : "r"(bbase + nb * 16));
                asm volatile("mma.sync.aligned.m16n8k16.row.col.f32.bf16.bf16.f32 "
                             "{%0,%1,%2,%3},{%4,%5,%6,%7},{%8,%9},{%0,%1,%2,%3};"
                             : "+f"(acc[nb][0]), "+f"(acc[nb][1]), "+f"(acc[nb][2]), "+f"(acc[nb][3])
                             : "r"(a[0]), "r"(a[1]), "r"(a[2]), "r"(a[3]), "r"(b[0]), "r"(b[1]));
            }
        }
        __syncthreads();
    }

    // staged epilogue: two 64-row passes through Os
    int c4 = t & 31;
    float4 bias4 = reinterpret_cast<const float4*>(bias)[c4];
    float sA[4] = {0.f, 0.f, 0.f, 0.f};
    float qA[4] = {0.f, 0.f, 0.f, 0.f};
    #pragma unroll
    for (int p = 0; p < 2; p++) {
        if ((wid >> 2) == p) {
            int r0 = (wid & 3) * 16 + (lane >> 2);
            #pragma unroll
            for (int nb = 0; nb < 16; nb++) {
                int c = nb * 8 + (lane & 3) * 2;
                *reinterpret_cast<float2*>(&Os[r0][c])     = make_float2(acc[nb][0], acc[nb][1]);
                *reinterpret_cast<float2*>(&Os[r0 + 8][c]) = make_float2(acc[nb][2], acc[nb][3]);
            }
        }
        __syncthreads();
        #pragma unroll
        for (int it = 0; it < 8; it++) {
            int r = it * 8 + wid;
            int grow = rowbase + p * 64 + r;
            if (grow < NN) {
                float4 rv = reinterpret_cast<const float4*>(d_rst)[grow * 32 + c4];
                float4 av = *reinterpret_cast<const float4*>(&Os[r][c4 * 4]);
                float4 y;
                y.x = OMBF * rv.x + BETAF * av.x + bias4.x;
                y.y = OMBF * rv.y + BETAF * av.y + bias4.y;
                y.z = OMBF * rv.z + BETAF * av.z + bias4.z;
                y.w = OMBF * rv.w + BETAF * av.w + bias4.w;
                reinterpret_cast<float4*>(d_rst)[grow * 32 + c4] = y;
                sA[0] += y.x; qA[0] += y.x * y.x;
                sA[1] += y.y; qA[1] += y.y * y.y;
                sA[2] += y.z; qA[2] += y.z * y.z;
                sA[3] += y.w; qA[3] += y.w * y.w;
            }
        }
        __syncthreads();
    }
    #pragma unroll
    for (int j = 0; j < 4; j++) {
        bns[wid][c4 * 4 + j]       = sA[j];
        bns[wid][128 + c4 * 4 + j] = qA[j];
    }
    __syncthreads();
    float v = 0.f;
    #pragma unroll
    for (int w = 0; w < 8; w++) v += bns[w][t];
    atomicAdd(&bnslot[t], v);
}

// ---------------- readout ----------------
__global__ void final_kernel(const float* __restrict__ lin_w,
                             const float* __restrict__ lin_b,
                             float* __restrict__ out) {
    __shared__ float sp[6][128];
    __shared__ float sc[NOUT];
    int g = blockIdx.x, t = threadIdx.x;   // 128 threads
    for (int i = t; i < 6 * 128; i += 128)
        sp[i / 128][i & 127] = d_pooled[((i / 128) * NG + g) * 128 + (i & 127)];
    __syncthreads();
    if (t < NOUT) {
        float s = 0.f;
        for (int i = 0; i < 6; i++) {
            s += lin_b[i * NOUT + t];
            const float* w = lin_w + i * 128 * NOUT;
            float ps = 0.f;
            for (int k = 0; k < 128; k++) ps += sp[i][k] * w[k * NOUT + t];
            s += ps;
        }
        sc[t] = s;
    }
    __syncthreads();
    if (t < NOUT) {
        float m = sc[0];
        #pragma unroll
        for (int i = 1; i < NOUT; i++) m = fmaxf(m, sc[i]);
        float lse = 0.f;
        #pragma unroll
        for (int i = 0; i < NOUT; i++) lse += expf(sc[i] - m);
        lse = logf(lse);
        out[g * NOUT + t] = sc[t] - m - lse;
    }
    float mp = sp[1][t] + sp[2][t] + sp[3][t] + sp[4][t] + sp[5][t];
    out[NG * NOUT + g * 128 + t] = mp * 0.2f;
}

// ---------------- trailing cleanup: restore zero state for next replay -----
__global__ void cleanup_kernel() {
    int i = blockIdx.x * blockDim.x + threadIdx.x;
    if (i < NN) { d_deg_out[i] = 0; d_deg_in[i] = 0; }
    if (i < (NLAY+1)*NG*DD) d_pooled[i] = 0.f;
    if (i < NLAY*2*DD) d_bnsum[i] = 0.f;
    if (i < NBLK) d_pub[i] = 0;
}

// ---------------- host launcher ----------------
extern "C" void kernel_launch(void* const* d_in, const int* in_sizes, int n_in,
                              void* d_out, int out_size) {
    const float* feat  = (const float*)d_in[0];
    const int*   src   = (const int*)  d_in[1];
    const int*   dst   = (const int*)  d_in[2];
    const int*   gid   = (const int*)  d_in[3];
    const float* gcn_w = (const float*)d_in[4];
    const float* gcn_b = (const float*)d_in[5];
    const float* bn_g  = (const float*)d_in[6];
    const float* bn_b  = (const float*)d_in[7];
    const float* lin_w = (const float*)d_in[8];
    const float* lin_b = (const float*)d_in[9];
    float* out = (float*)d_out;
    (void)in_sizes; (void)n_in; (void)out_size;

    float* bnsum_base;
    cudaGetSymbolAddress((void**)&bnsum_base, d_bnsum);
    __nv_bfloat16* wb_base;
    cudaGetSymbolAddress((void**)&wb_base, d_wb);

    deg_kernel<<<(NE + 255) / 256, 256>>>(src, dst);                      // idx 0
    scan_fused<<<NBLK, 256>>>();                                          // idx 1
    fill_epi_kernel<<<FILL_BLKS + EPI_BLKS, 512>>>(src, dst, feat, gid);  // idx 2

    for (int l = 0; l < NLAY; l++) {
        spmm_kernel<<<(NN * 32 + 255) / 256, 256>>>();                    // first = idx 3
        if (l == 0)
            wconv_kernel<<<(NLAY * DD * DD + 255) / 256, 256>>>(gcn_w);
        gemm_kernel<<<(NN + 127) / 128, 256>>>(wb_base + l * DD * DD,
                                               gcn_b + l * DD,
                                               bnsum_base + l * 2 * DD);
        epilogue_kernel<<<EPI_BLKS, 512>>>(gid, l + 1,
                                           bn_g + l * DD, bn_b + l * DD,
                                           bnsum_base + l * 2 * DD,
                                           (l < NLAY - 1) ? 1 : 0);
    }
    final_kernel<<<NG, 128>>>(lin_w, lin_b, out);
    cleanup_kernel<<<600, 256>>>();
}

// round 13
// speedup vs baseline: 1.9034x; 1.1830x over previous
#include <cuda_runtime.h>
#include <cuda_fp16.h>
#include <cuda_bf16.h>
#include <cstdint>

#define NN   100000
#define NE   600000
#define DD   128
#define NG   200
#define NLAY 5
#define NOUT 10
#define NBLK 98                 // ceil(NN/1024)
#define FILL_BLKS 1172          // ceil(NE/512)
#define EPI_BLKS  391           // ceil(NN/256)
#define GEMM_SMEM 69632         // As(34816) + Ws(34816)
#define BETAF 0.0077821404f     // ln(1 + 1/128)
#define OMBF  0.9922178596f     // 1 - BETA

// ---------------- scratch (device globals; no allocations) ----------------
// Zero-initialized at load; cleanup_kernel re-zeros at the END of every launch.
__device__ __align__(16) __half d_hsh [NN*DD];  // fp16: h * norm_out (gather table)
__device__ __align__(16) __half d_rsth[NN*DD];  // fp16: rst / y pipeline
__device__ __align__(16) __half d_wh[NLAY*DD*DD];  // fp16 weights
__device__ float d_norm_out[NN];
__device__ float d_sdeg[NN];
__device__ float d_norm_in [NN];
__device__ int   d_deg_out[NN];
__device__ int   d_deg_in [NN];
__device__ int   d_rowptr[NN+1];
__device__ int   d_cursor[NN];
__device__ int   d_col[NE];
__device__ float d_pooled[(NLAY+1)*NG*DD];
__device__ float d_bnsum[NLAY*2*DD];
__device__ int   d_pub[NBLK];                  // decoupled-lookback publish words

// ---------------- degree histogram ----------------
__global__ void deg_kernel(const int* __restrict__ src, const int* __restrict__ dst) {
    int i = blockIdx.x * blockDim.x + threadIdx.x;
    if (i < NE) {
        atomicAdd(&d_deg_out[src[i]], 1);
        atomicAdd(&d_deg_in [dst[i]], 1);
    }
}

// ---------------- fused norms + single-pass exclusive scan (lookback) -------
__global__ __launch_bounds__(256) void scan_fused() {
    __shared__ int sh[256];
    __shared__ int spre[128];
    int t = threadIdx.x, b = blockIdx.x, base = b * 1024;

    int loc[4]; int s = 0;
    #pragma unroll
    for (int i = 0; i < 4; i++) {
        int idx = base + t * 4 + i;
        int v = 0;
        if (idx < NN) {
            int dgo = max(d_deg_out[idx], 1);
            d_norm_out[idx] = rsqrtf((float)dgo);
            d_sdeg[idx]     = sqrtf((float)dgo);
            v = d_deg_in[idx];
            d_norm_in[idx]  = rsqrtf((float)max(v, 1));
        }
        loc[i] = s; s += v;
    }
    sh[t] = s; __syncthreads();
    for (int off = 1; off < 256; off <<= 1) {
        int v = (t >= off) ? sh[t - off] : 0;
        __syncthreads();
        sh[t] += v;
        __syncthreads();
    }
    if (t == 0) atomicExch(&d_pub[b], sh[255] + 1);

    int myagg = 0;
    if (t < b) {
        volatile int* p = &d_pub[t];
        int v;
        do { v = *p; } while (v == 0);
        myagg = v - 1;
    }
    if (t < 128) spre[t] = myagg;
    __syncthreads();
    for (int off = 64; off > 0; off >>= 1) {
        if (t < off) spre[t] += spre[t + off];
        __syncthreads();
    }
    int bpre = spre[0];

    int tpre = (t == 0) ? 0 : sh[t - 1];
    #pragma unroll
    for (int i = 0; i < 4; i++) {
        int idx = base + t * 4 + i;
        if (idx < NN) { int p = bpre + tpre + loc[i]; d_rowptr[idx] = p; d_cursor[idx] = p; }
    }
    if (b == 0 && t == 0) d_rowptr[NN] = NE;
}

// ---------------- W fp32 -> fp16 (all layers) ----------------
__global__ void wconv_kernel(const float* __restrict__ gcn_w) {
    int i = blockIdx.x * blockDim.x + threadIdx.x;
    if (i < NLAY * DD * DD) d_wh[i] = __float2half_rn(gcn_w[i]);
}

// ---------------- BN+ReLU epilogue body ----------------
// INIT: src fp32 feat. Non-INIT: reads fp16 y from d_rsth.
template <bool INIT, int TPB>
__device__ __forceinline__ void epilogue_body(const float* __restrict__ src,
                                              const int* __restrict__ gid,
                                              int pslot,
                                              const float* __restrict__ bng,
                                              const float* __restrict__ bnb,
                                              const float* __restrict__ bnslot,
                                              int blk, bool write_hs) {
    __shared__ float spool[16][128];
    const int QW = TPB / 128;
    int t = threadIdx.x;
    int base = blk * 256;
    int nodes = min(256, NN - base);
    if (nodes <= 0) return;
    int g0 = gid[base];
    int span = gid[base + nodes - 1] - g0 + 1;
    bool fits = (span <= 16);
    if (fits) for (int i = t; i < span * 128; i += TPB) ((float*)spool)[i] = 0.f;
    __syncthreads();

    int d = t & 127;
    int q = t >> 7;
    float bg = 0.f, bb = 0.f, mu = 0.f, is = 0.f;
    if (!INIT) {
        bg = bng[d]; bb = bnb[d];
        float s = bnslot[d], sq = bnslot[128 + d];
        mu = s * (1.0f / NN);
        is = rsqrtf(sq * (1.0f / NN) - mu * mu + 1e-5f);
    }

    float racc = 0.f; int rlg = -1;
    for (int i = q; i < nodes; i += QW) {
        int n = base + i;
        float y;
        if (INIT) y = src[n * 128 + d];
        else {
            float v = __half2float(d_rsth[n * 128 + d]);
            y = fmaxf((v - mu) * is * bg + bb, 0.0f);
        }
        if (write_hs) d_hsh[n * 128 + d] = __float2half_rn(y * d_norm_out[n]);
        int lg = gid[n] - g0;
        if (fits) {
            if (lg != rlg) {
                if (rlg >= 0) atomicAdd(&spool[rlg][d], racc);
                rlg = lg; racc = 0.f;
            }
            racc += y;
        } else {
            atomicAdd(&d_pooled[(pslot * NG + g0 + lg) * 128 + d], y);
        }
    }
    if (fits && rlg >= 0) atomicAdd(&spool[rlg][d], racc);
    __syncthreads();
    if (fits)
        for (int lg = q; lg < span; lg += QW)
            atomicAdd(&d_pooled[(pslot * NG + g0 + lg) * 128 + d], spool[lg][d]);
}

// fused: CSR fill (blocks [0,FILL_BLKS)) + init epilogue (blocks after)
__global__ __launch_bounds__(512) void fill_epi_kernel(const int* __restrict__ src,
                                                       const int* __restrict__ dst,
                                                       const float* __restrict__ feat,
                                                       const int* __restrict__ gid) {
    if (blockIdx.x < FILL_BLKS) {
        int i = blockIdx.x * 512 + threadIdx.x;
        if (i < NE) {
            int d = dst[i];
            int pos = atomicAdd(&d_cursor[d], 1);
            d_col[pos] = src[i];
        }
    } else {
        epilogue_body<true, 512>(feat, gid, 0, nullptr, nullptr, nullptr,
                                 blockIdx.x - FILL_BLKS, true);
    }
}

__global__ __launch_bounds__(512) void epilogue_kernel(const int* __restrict__ gid,
                                                       int pslot,
                                                       const float* __restrict__ bng,
                                                       const float* __restrict__ bnb,
                                                       const float* __restrict__ bnslot,
                                                       int write_hs) {
    epilogue_body<false, 512>(nullptr, gid, pslot, bng, bnb, bnslot,
                              blockIdx.x, write_hs != 0);
}

// ---------------- SpMM: warp per dst node, fp16 HADD2, fp16 output ---------
__global__ __launch_bounds__(256) void spmm_kernel() {
    int warp = (blockIdx.x * blockDim.x + threadIdx.x) >> 5;
    int lane = threadIdx.x & 31;
    if (warp >= NN) return;
    int beg = d_rowptr[warp], end = d_rowptr[warp + 1];
    float4 acc = make_float4(0.f, 0.f, 0.f, 0.f);
    const __half* hs = d_hsh;

    for (int e0 = beg; e0 < end; e0 += 32) {
        int m = min(32, end - e0);
        int c = (lane < m) ? __ldg(&d_col[e0 + lane]) : 0;
        __half2 a0 = __float2half2_rn(0.f), a1 = a0;
        int j = 0;
        for (; j + 4 <= m; j += 4) {
            int s0 = __shfl_sync(0xffffffffu, c, j);
            int s1 = __shfl_sync(0xffffffffu, c, j + 1);
            int s2 = __shfl_sync(0xffffffffu, c, j + 2);
            int s3 = __shfl_sync(0xffffffffu, c, j + 3);
            uint2 u0 = *reinterpret_cast<const uint2*>(hs + s0 * 128 + lane * 4);
            uint2 u1 = *reinterpret_cast<const uint2*>(hs + s1 * 128 + lane * 4);
            uint2 u2 = *reinterpret_cast<const uint2*>(hs + s2 * 128 + lane * 4);
            uint2 u3 = *reinterpret_cast<const uint2*>(hs + s3 * 128 + lane * 4);
            a0 = __hadd2(a0, *reinterpret_cast<__half2*>(&u0.x));
            a1 = __hadd2(a1, *reinterpret_cast<__half2*>(&u0.y));
            a0 = __hadd2(a0, *reinterpret_cast<__half2*>(&u1.x));
            a1 = __hadd2(a1, *reinterpret_cast<__half2*>(&u1.y));
            a0 = __hadd2(a0, *reinterpret_cast<__half2*>(&u2.x));
            a1 = __hadd2(a1, *reinterpret_cast<__half2*>(&u2.y));
            a0 = __hadd2(a0, *reinterpret_cast<__half2*>(&u3.x));
            a1 = __hadd2(a1, *reinterpret_cast<__half2*>(&u3.y));
        }
        for (; j < m; j++) {
            int s = __shfl_sync(0xffffffffu, c, j);
            uint2 u = *reinterpret_cast<const uint2*>(hs + s * 128 + lane * 4);
            a0 = __hadd2(a0, *reinterpret_cast<__half2*>(&u.x));
            a1 = __hadd2(a1, *reinterpret_cast<__half2*>(&u.y));
        }
        float2 f0 = __half22float2(a0);
        float2 f1 = __half22float2(a1);
        acc.x += f0.x; acc.y += f0.y; acc.z += f1.x; acc.w += f1.y;
    }
    float ni = 0.9f * d_norm_in[warp];
    float rs = 0.1f * d_sdeg[warp];
    uint2 u = *reinterpret_cast<const uint2*>(hs + warp * 128 + lane * 4);
    float2 h0 = __half22float2(*reinterpret_cast<__half2*>(&u.x));
    float2 h1 = __half22float2(*reinterpret_cast<__half2*>(&u.y));
    __half2 r0 = __floats2half2_rn(ni * acc.x + rs * h0.x, ni * acc.y + rs * h0.y);
    __half2 r1 = __floats2half2_rn(ni * acc.z + rs * h1.x, ni * acc.w + rs * h1.y);
    uint2 o;
    o.x = *reinterpret_cast<uint32_t*>(&r0);
    o.y = *reinterpret_cast<uint32_t*>(&r1);
    *reinterpret_cast<uint2*>(d_rsth + warp * 128 + lane * 4) = o;
}

// ---------------- GEMM: y = (1-B)*rst + B*(rst@W) + bias (fp16 pipeline) ---
// A staged fp16 from d_rsth (single K=128 pass, dynamic smem); f16 mma;
// residual read from the As smem tile (no global re-read); y written fp16.
__global__ __launch_bounds__(256) void gemm_kernel(const __half* __restrict__ Wh,
                                                   const float* __restrict__ bias,
                                                   float* __restrict__ bnslot) {
    extern __shared__ __align__(16) char dsm[];
    __half (*As)[136] = reinterpret_cast<__half(*)[136]>(dsm);           // 34816B
    __half (*Ws)[136] = reinterpret_cast<__half(*)[136]>(dsm + 34816);   // 34816B
    float  (*Os)[132] = reinterpret_cast<float(*)[132]>(dsm + 34816);    // alias Ws (33792B)
    __shared__ float bns[8][256];
    int t = threadIdx.x, lane = t & 31, wid = t >> 5;
    int rowbase = blockIdx.x * 128;
    float acc[16][4];
    #pragma unroll
    for (int i = 0; i < 16; i++) { acc[i][0]=0.f; acc[i][1]=0.f; acc[i][2]=0.f; acc[i][3]=0.f; }

    // stage A (128x128 fp16, direct copy) and W (128x128 fp16)
    for (int i = t; i < 128 * 16; i += 256) {
        int r = i >> 4, c8 = i & 15;
        int grow = rowbase + r;
        uint4 v = make_uint4(0u, 0u, 0u, 0u);
        if (grow < NN)
            v = reinterpret_cast<const uint4*>(d_rsth + grow * 128)[c8];
        *reinterpret_cast<uint4*>(&As[r][c8 * 8]) = v;
    }
    for (int i = t; i < 128 * 16; i += 256) {
        int r = i >> 4, c8 = i & 15;
        uint4 v = reinterpret_cast<const uint4*>(Wh + r * 128)[c8];
        *reinterpret_cast<uint4*>(&Ws[r][c8 * 8]) = v;
    }
    __syncthreads();

    #pragma unroll
    for (int k0 = 0; k0 < 128; k0 += 16) {
        uint32_t a[4];
        unsigned aaddr = (unsigned)__cvta_generic_to_shared(
            &As[wid * 16 + (lane & 15)][k0 + ((lane >> 1) & 8)]);
        asm volatile("ldmatrix.sync.aligned.m8n8.x4.shared.b16 {%0,%1,%2,%3}, [%4];"
                     : "=r"(a[0]), "=r"(a[1]), "=r"(a[2]), "=r"(a[3]) : "r"(aaddr));
        unsigned bbase = (unsigned)__cvta_generic_to_shared(&Ws[k0 + (lane & 15)][0]);
        #pragma unroll
        for (int nb = 0; nb < 16; nb++) {
            uint32_t b[2];
            asm volatile("ldmatrix.sync.aligned.m8n8.x2.trans.shared.b16 {%0,%1}, [%2];"
                         : "=r"(b[0]), "=r"(b[1]) : "r"(bbase + nb * 16));
            asm volatile("mma.sync.aligned.m16n8k16.row.col.f32.f16.f16.f32 "
                         "{%0,%1,%2,%3},{%4,%5,%6,%7},{%8,%9},{%0,%1,%2,%3};"
                         : "+f"(acc[nb][0]), "+f"(acc[nb][1]), "+f"(acc[nb][2]), "+f"(acc[nb][3])
                         : "r"(a[0]), "r"(a[1]), "r"(a[2]), "r"(a[3]), "r"(b[0]), "r"(b[1]));
        }
    }
    __syncthreads();   // Ws reads done; Os may alias

    // staged epilogue: two 64-row passes; residual from As; fp16 y out
    int c4 = t & 31;
    float4 bias4 = reinterpret_cast<const float4*>(bias)[c4];
    float sA[4] = {0.f, 0.f, 0.f, 0.f};
    float qA[4] = {0.f, 0.f, 0.f, 0.f};
    #pragma unroll
    for (int p = 0; p < 2; p++) {
        if ((wid >> 2) == p) {
            int r0 = (wid & 3) * 16 + (lane >> 2);
            #pragma unroll
            for (int nb = 0; nb < 16; nb++) {
                int c = nb * 8 + (lane & 3) * 2;
                *reinterpret_cast<float2*>(&Os[r0][c])     = make_float2(acc[nb][0], acc[nb][1]);
                *reinterpret_cast<float2*>(&Os[r0 + 8][c]) = make_float2(acc[nb][2], acc[nb][3]);
            }
        }
        __syncthreads();
        #pragma unroll
        for (int it = 0; it < 8; it++) {
            int r = it * 8 + wid;
            int grow = rowbase + p * 64 + r;
            if (grow < NN) {
                uint2 hu = *reinterpret_cast<const uint2*>(&As[p * 64 + r][c4 * 4]);
                float2 rv0 = __half22float2(*reinterpret_cast<__half2*>(&hu.x));
                float2 rv1 = __half22float2(*reinterpret_cast<__half2*>(&hu.y));
                float4 av = *reinterpret_cast<const float4*>(&Os[r][c4 * 4]);
                float y0 = OMBF * rv0.x + BETAF * av.x + bias4.x;
                float y1 = OMBF * rv0.y + BETAF * av.y + bias4.y;
                float y2 = OMBF * rv1.x + BETAF * av.z + bias4.z;
                float y3 = OMBF * rv1.y + BETAF * av.w + bias4.w;
                __half2 o0 = __floats2half2_rn(y0, y1);
                __half2 o1 = __floats2half2_rn(y2, y3);
                uint2 o;
                o.x = *reinterpret_cast<uint32_t*>(&o0);
                o.y = *reinterpret_cast<uint32_t*>(&o1);
                *reinterpret_cast<uint2*>(d_rsth + grow * 128 + c4 * 4) = o;
                sA[0] += y0; qA[0] += y0 * y0;
                sA[1] += y1; qA[1] += y1 * y1;
                sA[2] += y2; qA[2] += y2 * y2;
                sA[3] += y3; qA[3] += y3 * y3;
            }
        }
        __syncthreads();
    }
    #pragma unroll
    for (int j = 0; j < 4; j++) {
        bns[wid][c4 * 4 + j]       = sA[j];
        bns[wid][128 + c4 * 4 + j] = qA[j];
    }
    __syncthreads();
    float v = 0.f;
    #pragma unroll
    for (int w = 0; w < 8; w++) v += bns[w][t];
    atomicAdd(&bnslot[t], v);
}

// ---------------- readout ----------------
__global__ void final_kernel(const float* __restrict__ lin_w,
                             const float* __restrict__ lin_b,
                             float* __restrict__ out) {
    __shared__ float sp[6][128];
    __shared__ float sc[NOUT];
    int g = blockIdx.x, t = threadIdx.x;   // 128 threads
    for (int i = t; i < 6 * 128; i += 128)
        sp[i / 128][i & 127] = d_pooled[((i / 128) * NG + g) * 128 + (i & 127)];
    __syncthreads();
    if (t < NOUT) {
        float s = 0.f;
        for (int i = 0; i < 6; i++) {
            s += lin_b[i * NOUT + t];
            const float* w = lin_w + i * 128 * NOUT;
            float ps = 0.f;
            for (int k = 0; k < 128; k++) ps += sp[i][k] * w[k * NOUT + t];
            s += ps;
        }
        sc[t] = s;
    }
    __syncthreads();
    if (t < NOUT) {
        float m = sc[0];
        #pragma unroll
        for (int i = 1; i < NOUT; i++) m = fmaxf(m, sc[i]);
        float lse = 0.f;
        #pragma unroll
        for (int i = 0; i < NOUT; i++) lse += expf(sc[i] - m);
        lse = logf(lse);
        out[g * NOUT + t] = sc[t] - m - lse;
    }
    float mp = sp[1][t] + sp[2][t] + sp[3][t] + sp[4][t] + sp[5][t];
    out[NG * NOUT + g * 128 + t] = mp * 0.2f;
}

// ---------------- trailing cleanup: restore zero state for next replay -----
__global__ void cleanup_kernel() {
    int i = blockIdx.x * blockDim.x + threadIdx.x;
    if (i < NN) { d_deg_out[i] = 0; d_deg_in[i] = 0; }
    if (i < (NLAY+1)*NG*DD) d_pooled[i] = 0.f;
    if (i < NLAY*2*DD) d_bnsum[i] = 0.f;
    if (i < NBLK) d_pub[i] = 0;
}

// ---------------- host launcher ----------------
extern "C" void kernel_launch(void* const* d_in, const int* in_sizes, int n_in,
                              void* d_out, int out_size) {
    const float* feat  = (const float*)d_in[0];
    const int*   src   = (const int*)  d_in[1];
    const int*   dst   = (const int*)  d_in[2];
    const int*   gid   = (const int*)  d_in[3];
    const float* gcn_w = (const float*)d_in[4];
    const float* gcn_b = (const float*)d_in[5];
    const float* bn_g  = (const float*)d_in[6];
    const float* bn_b  = (const float*)d_in[7];
    const float* lin_w = (const float*)d_in[8];
    const float* lin_b = (const float*)d_in[9];
    float* out = (float*)d_out;
    (void)in_sizes; (void)n_in; (void)out_size;

    float* bnsum_base;
    cudaGetSymbolAddress((void**)&bnsum_base, d_bnsum);
    __half* wh_base;
    cudaGetSymbolAddress((void**)&wh_base, d_wh);

    cudaFuncSetAttribute(gemm_kernel, cudaFuncAttributeMaxDynamicSharedMemorySize,
                         GEMM_SMEM);

    deg_kernel<<<(NE + 255) / 256, 256>>>(src, dst);                      // idx 0
    scan_fused<<<NBLK, 256>>>();                                          // idx 1
    fill_epi_kernel<<<FILL_BLKS + EPI_BLKS, 512>>>(src, dst, feat, gid);  // idx 2

    for (int l = 0; l < NLAY; l++) {
        spmm_kernel<<<(NN * 32 + 255) / 256, 256>>>();                    // first = idx 3
        if (l == 0)
            wconv_kernel<<<(NLAY * DD * DD + 255) / 256, 256>>>(gcn_w);
        gemm_kernel<<<(NN + 127) / 128, 256, GEMM_SMEM>>>(wh_base + l * DD * DD,
                                                          gcn_b + l * DD,
                                                          bnsum_base + l * 2 * DD);
        epilogue_kernel<<<EPI_BLKS, 512>>>(gid, l + 1,
                                           bn_g + l * DD, bn_b + l * DD,
                                           bnsum_base + l * 2 * DD,
                                           (l < NLAY - 1) ? 1 : 0);
    }
    final_kernel<<<NG, 128>>>(lin_w, lin_b, out);
    cleanup_kernel<<<600, 256>>>();
}